// round 16
// baseline (speedup 1.0000x reference)
#include <cuda_runtime.h>
#include <cuda_fp16.h>
#include <cstdint>

#define MTOK 8192
#define HID  2048
#define ITR  8192
#define NB   4
#define SEQ  2048
#define KSAVE 10
#define FLAG_CAP (1<<20)
#define FIX_TAU 1.5e-3f

#define BN 256
#define BK 32
#define NSTAGE 3
#define NT 512

// ---------------- device scratch ----------------
__device__ __half g_x1h[(size_t)MTOK * HID];
__device__ __half g_wupT[(size_t)ITR * HID];       // fp16 [N][K]
__device__ float  g_wupT32[(size_t)ITR * HID];     // fp32 [N][K] for exact fixup
__device__ __half g_x2h[(size_t)MTOK * ITR];       // fp16 relu(y1)
__device__ __half g_wdnT[(size_t)HID * ITR];       // fp16 [N][K]
__device__ float g_pup[MTOK * 16];
__device__ float g_pdn[MTOK * 16];
__device__ int   g_counts[NB * ITR];
__device__ int   g_topk[NB * KSAVE];
__device__ int   g_nflag;
__device__ int   g_flagm[FLAG_CAP];
__device__ int   g_flagc[FLAG_CAP];

// ---------------- helpers ----------------
__device__ __forceinline__ void ldsm4(uint32_t& r0, uint32_t& r1, uint32_t& r2, uint32_t& r3, uint32_t addr) {
    asm volatile("ldmatrix.sync.aligned.m8n8.x4.shared.b16 {%0,%1,%2,%3}, [%4];\n"
                 : "=r"(r0), "=r"(r1), "=r"(r2), "=r"(r3) : "r"(addr));
}
__device__ __forceinline__ void mma16816(float* d, const uint32_t* a, const uint32_t* b) {
    asm volatile("mma.sync.aligned.m16n8k16.row.col.f32.f16.f16.f32 "
                 "{%0,%1,%2,%3}, {%4,%5,%6,%7}, {%8,%9}, {%0,%1,%2,%3};\n"
                 : "+f"(d[0]), "+f"(d[1]), "+f"(d[2]), "+f"(d[3])
                 : "r"(a[0]), "r"(a[1]), "r"(a[2]), "r"(a[3]), "r"(b[0]), "r"(b[1]));
}

// ---------------- lora projection + global init (launch #1) ----------------
__global__ void lora_proj_init(const float* __restrict__ A, const float* __restrict__ Wl,
                               float* __restrict__ P, int K) {
    int gi = blockIdx.x * 256 + threadIdx.x;
    if (gi == 0) g_nflag = 0;
    if (gi < NB * ITR) g_counts[gi] = 0;
    g_pdn[gi] = 0.f;

    int row = blockIdx.x * 16 + (threadIdx.x >> 4);
    int r   = threadIdx.x & 15;
    const float* a = A + (size_t)row * K;
    float acc = 0.f;
    for (int k = 0; k < K; k += 4) {
        float4 av = *(const float4*)(a + k);
        acc += av.x * Wl[(k + 0) * 16 + r];
        acc += av.y * Wl[(k + 1) * 16 + r];
        acc += av.z * Wl[(k + 2) * 16 + r];
        acc += av.w * Wl[(k + 3) * 16 + r];
    }
    P[row * 16 + r] = acc;
}

// ---------------- fp32 -> fp16 ----------------
__global__ void to_half(const float* __restrict__ src, __half* __restrict__ dst, size_t n4) {
    size_t i = (size_t)blockIdx.x * 256 + threadIdx.x;
    if (i >= n4) return;
    float4 v = ((const float4*)src)[i];
    union { __half h[4]; uint2 u; } H;
    H.h[0] = __float2half_rn(v.x); H.h[1] = __float2half_rn(v.y);
    H.h[2] = __float2half_rn(v.z); H.h[3] = __float2half_rn(v.w);
    ((uint2*)dst)[i] = H.u;
}

// ---------------- fp32 [K][N] -> fp16 [N][K] transpose ----------------
__global__ void split_T(const float* __restrict__ src, __half* __restrict__ dh, int K, int N) {
    __shared__ float t[32][33];
    int bx = blockIdx.x, by = blockIdx.y;
    int x = threadIdx.x, y = threadIdx.y;   // 32 x 8
#pragma unroll
    for (int i = 0; i < 32; i += 8)
        t[y + i][x] = src[(size_t)(by * 32 + y + i) * N + bx * 32 + x];
    __syncthreads();
#pragma unroll
    for (int i = 0; i < 32; i += 8)
        dh[(size_t)(bx * 32 + y + i) * K + by * 32 + x] = __float2half_rn(t[x][y + i]);
}

// ---------------- fp32 [K][N] -> fp16 + fp32 [N][K] transpose (one read) ----------
__global__ void split_T_dual(const float* __restrict__ src, __half* __restrict__ dh,
                             float* __restrict__ df, int K, int N) {
    __shared__ float t[32][33];
    int bx = blockIdx.x, by = blockIdx.y;
    int x = threadIdx.x, y = threadIdx.y;
#pragma unroll
    for (int i = 0; i < 32; i += 8)
        t[y + i][x] = src[(size_t)(by * 32 + y + i) * N + bx * 32 + x];
    __syncthreads();
#pragma unroll
    for (int i = 0; i < 32; i += 8) {
        float v = t[x][y + i];
        size_t o = (size_t)(bx * 32 + y + i) * K + by * 32 + x;
        dh[o] = __float2half_rn(v);
        df[o] = v;
    }
}

// ---------------- fused fp16 GEMM (BMT x 256), 512 threads, frag double-buffer ----
template<int BMT, int SWAP, int EPI>
__global__ void __launch_bounds__(NT, 1) gemm_f16(
    const __half* __restrict__ gA, const __half* __restrict__ gB,
    const float* __restrict__ gL, const float* __restrict__ gBm,
    const float* __restrict__ gWdl,
    float* __restrict__ Y, __half* __restrict__ X2, int M, int N, int K)
{
    constexpr int MI = BMT / 64;             // m16 frags per warp (2 or 1)
    constexpr int ASTG = BMT * BK * 2;
    constexpr int BSTG = BN * BK * 2;
    constexpr int STG = ASTG + BSTG;
    extern __shared__ char smem[];
    const int tid = threadIdx.x, lane = tid & 31, wid = tid >> 5;   // 16 warps
    const int m0 = (SWAP ? blockIdx.y : blockIdx.x) * BMT;
    const int n0 = (SWAP ? blockIdx.x : blockIdx.y) * BN;
    const int warpM = (wid >> 2) * (BMT / 4), warpN = (wid & 3) * 64;
    const int rlo = lane & 15;

    float acc[MI][8][4];
#pragma unroll
    for (int mi = 0; mi < MI; mi++)
#pragma unroll
        for (int ni = 0; ni < 8; ni++)
#pragma unroll
            for (int q = 0; q < 4; q++) acc[mi][ni][q] = 0.f;

    auto stage_load = [&](int st, int k0) {
        char* base = smem + st * STG;
        {   // A: BMT*4 16B-chunks
            int c = tid;
            if (c < BMT * 4) {
                int row = c >> 2, c4 = c & 3;
                const __half* g = gA + (size_t)(m0 + row) * K + k0 + c4 * 8;
                uint32_t d = (uint32_t)__cvta_generic_to_shared(
                    base + row * 64 + ((c4 ^ ((row >> 1) & 3)) << 4));
                asm volatile("cp.async.cg.shared.global [%0], [%1], 16;\n" :: "r"(d), "l"(g));
            }
        }
#pragma unroll
        for (int i = 0; i < 2; i++) {          // B: 1024 chunks
            int c = tid + i * NT;
            int row = c >> 2, c4 = c & 3;
            const __half* g = gB + (size_t)(n0 + row) * K + k0 + c4 * 8;
            uint32_t d = (uint32_t)__cvta_generic_to_shared(
                base + ASTG + row * 64 + ((c4 ^ ((row >> 1) & 3)) << 4));
            asm volatile("cp.async.cg.shared.global [%0], [%1], 16;\n" :: "r"(d), "l"(g));
        }
        asm volatile("cp.async.commit_group;\n");
    };

    auto load_frags = [&](uint32_t base, int s, uint32_t aF[][4], uint32_t bF[][2]) {
        int c4 = s * 2 + (lane >> 4);
#pragma unroll
        for (int nj = 0; nj < 4; nj++) {
            int row = warpN + nj * 16 + rlo;
            uint32_t r0, r1, r2, r3;
            ldsm4(r0, r1, r2, r3, base + ASTG + row * 64 + ((c4 ^ ((row >> 1) & 3)) << 4));
            bF[2 * nj][0] = r0; bF[2 * nj][1] = r2;
            bF[2 * nj + 1][0] = r1; bF[2 * nj + 1][1] = r3;
        }
#pragma unroll
        for (int mi = 0; mi < MI; mi++) {
            int row = warpM + mi * 16 + rlo;
            ldsm4(aF[mi][0], aF[mi][1], aF[mi][2], aF[mi][3],
                  base + row * 64 + ((c4 ^ ((row >> 1) & 3)) << 4));
        }
    };

    auto mma_tile = [&](uint32_t aF[][4], uint32_t bF[][2]) {
#pragma unroll
        for (int mi = 0; mi < MI; mi++)
#pragma unroll
            for (int ni = 0; ni < 8; ni++) mma16816(acc[mi][ni], aF[mi], bF[ni]);
    };

    // ---- prologue ----
    stage_load(0, 0);
    stage_load(1, BK);
    asm volatile("cp.async.wait_group 1;\n");
    __syncthreads();

    uint32_t aF[2][MI][4], bF[2][8][2];
    load_frags((uint32_t)__cvta_generic_to_shared(smem), 0, aF[0], bF[0]);

    const int nIter = K / BK;
    for (int it = 0; it < nIter; it++) {
        uint32_t bCur = (uint32_t)__cvta_generic_to_shared(smem + (it % NSTAGE) * STG);
        uint32_t bNxt = (uint32_t)__cvta_generic_to_shared(smem + ((it + 1) % NSTAGE) * STG);
        bool more = (it + 2 < nIter);
        if (more) stage_load((it + 2) % NSTAGE, (it + 2) * BK);
        load_frags(bCur, 1, aF[1], bF[1]);       // s1 frags (stage ready)
        mma_tile(aF[0], bF[0]);                  // overlap with ldsm above
        if (more) asm volatile("cp.async.wait_group 1;\n");
        else      asm volatile("cp.async.wait_group 0;\n");
        __syncthreads();
        if (it + 1 < nIter) load_frags(bNxt, 0, aF[0], bF[0]);   // next-iter s0 frags
        mma_tile(aF[1], bF[1]);
    }

    // ---------------- epilogue: lora add (+ pdn/count/flag for EPI) ----------------
    float* sL   = (float*)smem;                               // [BMT][17]
    float* sB16 = (float*)(smem + BMT * 17 * 4);              // [16][260]
    float* sWdl = (float*)(smem + BMT * 17 * 4 + 16640);      // [256][17] (EPI only)
    for (int i = tid; i < BMT * 16; i += NT) {
        int rw = i >> 4, rr = i & 15;
        sL[rw * 17 + rr] = gL[(size_t)(m0 + rw) * 16 + rr];
    }
    for (int i = tid; i < 16 * BN; i += NT) {
        int rr = i >> 8, cc = i & 255;
        sB16[rr * 260 + cc] = gBm[(size_t)rr * N + n0 + cc];
    }
    if (EPI) {
        for (int i = tid; i < BN * 16; i += NT) {
            int cc = i >> 4, rr = i & 15;
            sWdl[cc * 17 + rr] = gWdl[(size_t)(n0 + cc) * 16 + rr];
        }
    }
    __syncthreads();
    const int r = lane >> 2, cb = (lane & 3) * 2;
#pragma unroll
    for (int rr = 0; rr < 16; rr++) {
        float Lv[2 * MI];
#pragma unroll
        for (int mi = 0; mi < MI; mi++) {
            Lv[2 * mi]     = sL[(warpM + mi * 16 + r) * 17 + rr];
            Lv[2 * mi + 1] = sL[(warpM + mi * 16 + r + 8) * 17 + rr];
        }
#pragma unroll
        for (int ni = 0; ni < 8; ni++) {
            float b0v = sB16[rr * 260 + warpN + ni * 8 + cb];
            float b1v = sB16[rr * 260 + warpN + ni * 8 + cb + 1];
#pragma unroll
            for (int mi = 0; mi < MI; mi++) {
                acc[mi][ni][0] += Lv[2 * mi] * b0v;     acc[mi][ni][1] += Lv[2 * mi] * b1v;
                acc[mi][ni][2] += Lv[2 * mi + 1] * b0v; acc[mi][ni][3] += Lv[2 * mi + 1] * b1v;
            }
        }
    }

    if (EPI) {
        int bidx = m0 >> 11;
#pragma unroll
        for (int ni = 0; ni < 8; ni++) {
            int c0 = 0, c1 = 0;
#pragma unroll
            for (int mi = 0; mi < MI; mi++) {
                c0 += (acc[mi][ni][0] <= -FIX_TAU) + (acc[mi][ni][2] <= -FIX_TAU);
                c1 += (acc[mi][ni][1] <= -FIX_TAU) + (acc[mi][ni][3] <= -FIX_TAU);
            }
            int packed = c0 | (c1 << 16);
            packed += __shfl_xor_sync(0xffffffffu, packed, 4);
            packed += __shfl_xor_sync(0xffffffffu, packed, 8);
            packed += __shfl_xor_sync(0xffffffffu, packed, 16);
            if (r == 0) {
                int col = n0 + warpN + ni * 8 + cb;
                atomicAdd(&g_counts[bidx * ITR + col], packed & 0xffff);
                atomicAdd(&g_counts[bidx * ITR + col + 1], packed >> 16);
            }
        }
#pragma unroll
        for (int rr = 0; rr < 16; rr++) {
            float s[2 * MI];
#pragma unroll
            for (int j = 0; j < 2 * MI; j++) s[j] = 0.f;
#pragma unroll
            for (int ni = 0; ni < 8; ni++) {
                float w0 = sWdl[(warpN + ni * 8 + cb) * 17 + rr];
                float w1 = sWdl[(warpN + ni * 8 + cb + 1) * 17 + rr];
#pragma unroll
                for (int mi = 0; mi < MI; mi++) {
                    s[2 * mi]     += fmaxf(acc[mi][ni][0], 0.f) * w0 + fmaxf(acc[mi][ni][1], 0.f) * w1;
                    s[2 * mi + 1] += fmaxf(acc[mi][ni][2], 0.f) * w0 + fmaxf(acc[mi][ni][3], 0.f) * w1;
                }
            }
#pragma unroll
            for (int j = 0; j < 2 * MI; j++) {
                s[j] += __shfl_xor_sync(0xffffffffu, s[j], 1);
                s[j] += __shfl_xor_sync(0xffffffffu, s[j], 2);
            }
            if ((lane & 3) == 0) {
#pragma unroll
                for (int mi = 0; mi < MI; mi++) {
                    atomicAdd(&g_pdn[(m0 + warpM + mi * 16 + r) * 16 + rr], s[2 * mi]);
                    atomicAdd(&g_pdn[(m0 + warpM + mi * 16 + r + 8) * 16 + rr], s[2 * mi + 1]);
                }
            }
        }
    }

    // ---------------- writeback ----------------
#pragma unroll
    for (int mi = 0; mi < MI; mi++) {
        int row0 = m0 + warpM + mi * 16 + r;
#pragma unroll
        for (int ni = 0; ni < 8; ni++) {
            int col = n0 + warpN + ni * 8 + cb;
            if (EPI) {
                __half2 h0 = __floats2half2_rn(fmaxf(acc[mi][ni][0], 0.f), fmaxf(acc[mi][ni][1], 0.f));
                __half2 h1 = __floats2half2_rn(fmaxf(acc[mi][ni][2], 0.f), fmaxf(acc[mi][ni][3], 0.f));
                *(__half2*)&X2[(size_t)row0 * N + col]       = h0;
                *(__half2*)&X2[(size_t)(row0 + 8) * N + col] = h1;
#pragma unroll
                for (int q = 0; q < 4; q++) {
                    bool t = fabsf(acc[mi][ni][q]) < FIX_TAU;
                    unsigned msk = __ballot_sync(0xffffffffu, t);
                    if (msk) {
                        int ldr = __ffs(msk) - 1;
                        int base = 0;
                        if (lane == ldr) base = atomicAdd(&g_nflag, __popc(msk));
                        base = __shfl_sync(0xffffffffu, base, ldr);
                        if (t) {
                            int off = base + __popc(msk & ((1u << lane) - 1));
                            if (off < FLAG_CAP) {
                                g_flagm[off] = row0 + ((q >= 2) ? 8 : 0);
                                g_flagc[off] = col + (q & 1);
                            }
                        }
                    }
                }
            } else {
                *(float2*)&Y[(size_t)row0 * N + col]       = make_float2(acc[mi][ni][0], acc[mi][ni][1]);
                *(float2*)&Y[(size_t)(row0 + 8) * N + col] = make_float2(acc[mi][ni][2], acc[mi][ni][3]);
            }
        }
    }
}

// ---------------- exact fp32 recompute of flagged elements ----------------
__global__ void fixup(const float* __restrict__ x1, const float* __restrict__ wT,
                      const float* __restrict__ w_up_lb) {
    int warpId = (blockIdx.x * blockDim.x + threadIdx.x) >> 5;
    int lane = threadIdx.x & 31;
    int totalWarps = (gridDim.x * blockDim.x) >> 5;
    int n = min(g_nflag, FLAG_CAP);
    for (int i = warpId; i < n; i += totalWarps) {
        int m = g_flagm[i], c = g_flagc[i];
        const float* xr = x1 + (size_t)m * HID;
        const float* wc = wT + (size_t)c * HID;
        float s = 0.f;
        for (int k = lane * 4; k < HID; k += 128) {
            float4 xv = *(const float4*)(xr + k);
            float4 wv = *(const float4*)(wc + k);
            s += xv.x * wv.x + xv.y * wv.y + xv.z * wv.z + xv.w * wv.w;
        }
#pragma unroll
        for (int o = 16; o > 0; o >>= 1) s += __shfl_xor_sync(0xffffffffu, s, o);
        if (lane == 0) {
#pragma unroll
            for (int rr = 0; rr < 16; rr++) s += g_pup[m * 16 + rr] * w_up_lb[rr * ITR + c];
            if (s <= 0.f) atomicAdd(&g_counts[(m >> 11) * ITR + c], 1);
            g_x2h[(size_t)m * ITR + c] = __float2half_rn(fmaxf(s, 0.f));
        }
    }
}

// ---------------- exact top-10 smallest (count, index) ----------------
__global__ void topk_kernel() {
    __shared__ int red[256];
    int b = blockIdx.x, tid = threadIdx.x;
    int prev = -1;
    for (int r = 0; r < KSAVE; r++) {
        int best = 0x7fffffff;
        for (int c = tid; c < ITR; c += 256) {
            int key = (g_counts[b * ITR + c] << 13) | c;
            if (key > prev && key < best) best = key;
        }
        red[tid] = best;
        __syncthreads();
        for (int s = 128; s > 0; s >>= 1) {
            if (tid < s) red[tid] = min(red[tid], red[tid + s]);
            __syncthreads();
        }
        prev = red[0];
        if (tid == 0) g_topk[b * KSAVE + r] = prev & 8191;
        __syncthreads();
    }
}

// ---------------- gather ----------------
__global__ void gather_save(float* __restrict__ outp) {
    int i = blockIdx.x * 256 + threadIdx.x;
    if (i >= NB * SEQ * KSAVE) return;
    int j = i % KSAVE;
    int s = (i / KSAVE) % SEQ;
    int b = i / (KSAVE * SEQ);
    int c = g_topk[b * KSAVE + j];
    outp[i] = __half2float(g_x2h[(size_t)(b * SEQ + s) * ITR + c]);
}

// ---------------- launch ----------------
extern "C" void kernel_launch(void* const* d_in, const int* in_sizes, int n_in,
                              void* d_out, int out_size) {
    const float* x1      = (const float*)d_in[0];
    const float* w_up    = (const float*)d_in[1];
    const float* w_up_la = (const float*)d_in[2];
    const float* w_up_lb = (const float*)d_in[3];
    const float* w_down  = (const float*)d_in[4];
    const float* w_dn_la = (const float*)d_in[5];
    const float* w_dn_lb = (const float*)d_in[6];
    float* out = (float*)d_out;

    float *pup, *pdn, *wupT32;
    __half *x1h, *wupT, *x2h, *wdnT;
    cudaGetSymbolAddress((void**)&pup, g_pup);
    cudaGetSymbolAddress((void**)&pdn, g_pdn);
    cudaGetSymbolAddress((void**)&x1h, g_x1h);
    cudaGetSymbolAddress((void**)&wupT, g_wupT);
    cudaGetSymbolAddress((void**)&wupT32, g_wupT32);
    cudaGetSymbolAddress((void**)&x2h, g_x2h);
    cudaGetSymbolAddress((void**)&wdnT, g_wdnT);

    constexpr int DS1 = NSTAGE * (128 * BK * 2 + BN * BK * 2);   // 73728
    constexpr int DS2 = NSTAGE * (64 * BK * 2 + BN * BK * 2);    // 61440
    cudaFuncSetAttribute(gemm_f16<128, 0, 1>, cudaFuncAttributeMaxDynamicSharedMemorySize, DS1);
    cudaFuncSetAttribute(gemm_f16<64, 1, 0>, cudaFuncAttributeMaxDynamicSharedMemorySize, DS2);

    // launch order: gemm1 is the 4th launch => profiled by ncu (-s window)
    lora_proj_init<<<MTOK / 16, 256>>>(x1, w_up_la, pup, HID);                   // 1
    {
        size_t n4 = (size_t)MTOK * HID / 4;
        to_half<<<(unsigned)((n4 + 255) / 256), 256>>>(x1, x1h, n4);             // 2
    }
    split_T_dual<<<dim3(ITR / 32, HID / 32), dim3(32, 8)>>>(w_up, wupT, wupT32, HID, ITR);  // 3
    gemm_f16<128, 0, 1><<<dim3(MTOK / 128, ITR / BN), NT, DS1>>>(                // 4  <-- profiled
        x1h, wupT, pup, w_up_lb, w_dn_la, (float*)nullptr, x2h, MTOK, ITR, HID);

    split_T<<<dim3(HID / 32, ITR / 32), dim3(32, 8)>>>(w_down, wdnT, ITR, HID);  // 5
    fixup<<<512, 256>>>(x1, wupT32, w_up_lb);                                    // 6
    topk_kernel<<<NB, 256>>>();                                                  // 7
    gemm_f16<64, 1, 0><<<dim3(HID / BN, MTOK / 64), NT, DS2>>>(                  // 8
        x2h, wdnT, pdn, w_dn_lb, (float*)nullptr, out, (__half*)nullptr, MTOK, HID, ITR);

    int save_elems = NB * SEQ * KSAVE;
    gather_save<<<(save_elems + 255) / 256, 256>>>(out + (out_size - save_elems)); // 9
}

// round 17
// speedup vs baseline: 1.1041x; 1.1041x over previous
#include <cuda_runtime.h>
#include <cuda_fp16.h>
#include <cstdint>

#define MTOK 8192
#define HID  2048
#define ITR  8192
#define NB   4
#define SEQ  2048
#define KSAVE 10
#define FLAG_CAP (1<<20)
#define FIX_TAU 1.5e-3f

#define BN 256
#define BK 32
#define NSTAGE 3
#define NT 512
#define BCHUNK 16384   // BN*BK*2

// ---------------- packed operand images (swizzled tile-contiguous) ----------------
__device__ char  g_x1p[(size_t)(MTOK/128) * (HID/32) * 8192];    // 32 MB
__device__ char  g_wupP[(size_t)(ITR/256) * (HID/32) * BCHUNK];  // 32 MB
__device__ char  g_wdnP[(size_t)(HID/256) * (ITR/32) * BCHUNK];  // 32 MB
__device__ char  g_x2p[(size_t)(MTOK/64) * (ITR/32) * 4096];     // 128 MB, BMT2=64 tiles
__device__ float g_wupT32[(size_t)ITR * HID];                    // fp32 [N][K] for fixup
__device__ float g_pup[MTOK * 16];
__device__ float g_pdn[MTOK * 16];
__device__ int   g_counts[NB * ITR];
__device__ int   g_topk[NB * KSAVE];
__device__ int   g_nflag;
__device__ int   g_flagm[FLAG_CAP];
__device__ int   g_flagc[FLAG_CAP];

// ---------------- helpers ----------------
__device__ __forceinline__ void ldsm4(uint32_t& r0, uint32_t& r1, uint32_t& r2, uint32_t& r3, uint32_t addr) {
    asm volatile("ldmatrix.sync.aligned.m8n8.x4.shared.b16 {%0,%1,%2,%3}, [%4];\n"
                 : "=r"(r0), "=r"(r1), "=r"(r2), "=r"(r3) : "r"(addr));
}
__device__ __forceinline__ void mma16816(float* d, const uint32_t* a, const uint32_t* b) {
    asm volatile("mma.sync.aligned.m16n8k16.row.col.f32.f16.f16.f32 "
                 "{%0,%1,%2,%3}, {%4,%5,%6,%7}, {%8,%9}, {%0,%1,%2,%3};\n"
                 : "+f"(d[0]), "+f"(d[1]), "+f"(d[2]), "+f"(d[3])
                 : "r"(a[0]), "r"(a[1]), "r"(a[2]), "r"(a[3]), "r"(b[0]), "r"(b[1]));
}
__device__ __forceinline__ void mbar_init(uint32_t a, uint32_t c) {
    asm volatile("mbarrier.init.shared.b64 [%0], %1;" :: "r"(a), "r"(c) : "memory");
}
__device__ __forceinline__ void mbar_expect(uint32_t a, uint32_t b) {
    asm volatile("mbarrier.arrive.expect_tx.shared.b64 _, [%0], %1;" :: "r"(a), "r"(b) : "memory");
}
__device__ __forceinline__ void mbar_wait(uint32_t a, uint32_t p) {
    asm volatile(
        "{\n\t.reg .pred P;\n\t"
        "WL%=:\n\t"
        "mbarrier.try_wait.parity.acquire.cta.shared::cta.b64 P, [%0], %1, 0x989680;\n\t"
        "@P bra WD%=;\n\t"
        "bra WL%=;\n\t"
        "WD%=:\n\t}"
        :: "r"(a), "r"(p) : "memory");
}
__device__ __forceinline__ void bulk_g2s(uint32_t dst, const void* src, uint32_t bytes, uint32_t mbar) {
    asm volatile("cp.async.bulk.shared::cta.global.mbarrier::complete_tx::bytes [%0], [%1], %2, [%3];"
                 :: "r"(dst), "l"(src), "r"(bytes), "r"(mbar) : "memory");
}
// packed x2 address (BMT2=64 tiles, BK=32): byte offset of element (m, c)
__device__ __forceinline__ size_t x2_off(int m, int c) {
    int mt = m >> 6, row = m & 63, kt = c >> 5, cc = c & 31;
    int c4 = cc >> 3, j = cc & 7;
    return ((size_t)mt * (ITR / 32) + kt) * 4096
         + (uint32_t)(row * 64 + ((c4 ^ ((row >> 1) & 3)) << 4) + j * 2);
}

// ---------------- lora projection + global init (launch #1) ----------------
__global__ void lora_proj_init(const float* __restrict__ A, const float* __restrict__ Wl,
                               float* __restrict__ P, int K) {
    int gi = blockIdx.x * 256 + threadIdx.x;
    if (gi == 0) g_nflag = 0;
    if (gi < NB * ITR) g_counts[gi] = 0;
    g_pdn[gi] = 0.f;

    int row = blockIdx.x * 16 + (threadIdx.x >> 4);
    int r   = threadIdx.x & 15;
    const float* a = A + (size_t)row * K;
    float acc = 0.f;
    for (int k = 0; k < K; k += 4) {
        float4 av = *(const float4*)(a + k);
        acc += av.x * Wl[(k + 0) * 16 + r];
        acc += av.y * Wl[(k + 1) * 16 + r];
        acc += av.z * Wl[(k + 2) * 16 + r];
        acc += av.w * Wl[(k + 3) * 16 + r];
    }
    P[row * 16 + r] = acc;
}

// ---------------- pack A (fp32 [M][K] -> packed swizzled fp16 128x32 tiles) -------
__global__ void pack_A(const float* __restrict__ src, char* __restrict__ dst, int K) {
    int t = threadIdx.x;
    int mt = blockIdx.x, kt = blockIdx.y;
    int row = t >> 1, half = t & 1;
    const float* s = src + (size_t)(mt * 128 + row) * K + kt * 32 + half * 16;
    char* base = dst + ((size_t)mt * (K / 32) + kt) * 8192;
#pragma unroll
    for (int j2 = 0; j2 < 2; j2++) {
        float4 a = *(const float4*)(s + j2 * 8);
        float4 b = *(const float4*)(s + j2 * 8 + 4);
        union { __half h[8]; uint4 u; } H;
        H.h[0] = __float2half_rn(a.x); H.h[1] = __float2half_rn(a.y);
        H.h[2] = __float2half_rn(a.z); H.h[3] = __float2half_rn(a.w);
        H.h[4] = __float2half_rn(b.x); H.h[5] = __float2half_rn(b.y);
        H.h[6] = __float2half_rn(b.z); H.h[7] = __float2half_rn(b.w);
        int c4 = half * 2 + j2;
        uint32_t off = row * 64 + ((c4 ^ ((row >> 1) & 3)) << 4);
        *(uint4*)(base + off) = H.u;
    }
}

// ---------------- pack B (fp32 [K][N] -> packed swizzled fp16 256x32 K-major) -----
template<int WF32>
__global__ void pack_B(const float* __restrict__ src, char* __restrict__ dst,
                       float* __restrict__ df, int K, int N) {
    __shared__ float tb[32][260];
    int t = threadIdx.x;
    int nt = blockIdx.x, kt = blockIdx.y;
#pragma unroll
    for (int i = 0; i < 32; i++) {
        int idx = i * 256 + t;
        int kk = idx >> 8, nn = idx & 255;
        tb[kk][nn] = src[(size_t)(kt * 32 + kk) * N + nt * 256 + nn];
    }
    __syncthreads();
    char* base = dst + ((size_t)nt * (K / 32) + kt) * (size_t)BCHUNK;
    int row = t;
    float vals[32];
#pragma unroll
    for (int k = 0; k < 32; k++) vals[k] = tb[k][row];
#pragma unroll
    for (int c4 = 0; c4 < 4; c4++) {
        union { __half h[8]; uint4 u; } H;
#pragma unroll
        for (int j = 0; j < 8; j++) H.h[j] = __float2half_rn(vals[c4 * 8 + j]);
        uint32_t off = row * 64 + ((c4 ^ ((row >> 1) & 3)) << 4);
        *(uint4*)(base + off) = H.u;
    }
    if (WF32) {
        float* drow = df + (size_t)(nt * 256 + row) * K + kt * 32;
#pragma unroll
        for (int k = 0; k < 32; k += 4)
            *(float4*)(drow + k) = make_float4(vals[k], vals[k + 1], vals[k + 2], vals[k + 3]);
    }
}

// ---------------- fused fp16 GEMM (BMT x 256), bulk-copy pipeline ----------------
template<int BMT, int SWAP, int EPI>
__global__ void __launch_bounds__(NT, 1) gemm_f16(
    const char* __restrict__ gA, const char* __restrict__ gB,
    const float* __restrict__ gL, const float* __restrict__ gBm,
    const float* __restrict__ gWdl,
    float* __restrict__ Y, char* __restrict__ X2p, int M, int N, int K)
{
    constexpr int MI = BMT / 64;
    constexpr int ACHUNK = BMT * 64;       // BMT*32*2
    constexpr int STG = ACHUNK + BCHUNK;
    extern __shared__ char smem[];
    uint32_t sb = (uint32_t)__cvta_generic_to_shared(smem);
    const int tid = threadIdx.x, lane = tid & 31, wid = tid >> 5;
    const int m0 = (SWAP ? blockIdx.y : blockIdx.x) * BMT;
    const int n0 = (SWAP ? blockIdx.x : blockIdx.y) * BN;
    const int warpM = (wid >> 2) * (BMT / 4), warpN = (wid & 3) * 64;
    const int rlo = lane & 15;

    const char* Ap = gA + ((size_t)(m0 / BMT) * (K / BK)) * (size_t)ACHUNK;
    const char* Bp = gB + ((size_t)(n0 / BN) * (K / BK)) * (size_t)BCHUNK;

    float acc[MI][8][4];
#pragma unroll
    for (int mi = 0; mi < MI; mi++)
#pragma unroll
        for (int ni = 0; ni < 8; ni++)
#pragma unroll
            for (int q = 0; q < 4; q++) acc[mi][ni][q] = 0.f;

    if (tid == 0)
        for (int s = 0; s < NSTAGE; s++) mbar_init(sb + s * 8, 1);
    asm volatile("fence.proxy.async.shared::cta;" ::: "memory");
    __syncthreads();

    auto issue = [&](int it) {
        int s = it % NSTAGE;
        uint32_t bar = sb + s * 8;
        mbar_expect(bar, (uint32_t)STG);
        uint32_t dst = sb + 1024 + s * STG;
        bulk_g2s(dst, Ap + (size_t)it * ACHUNK, ACHUNK, bar);
        bulk_g2s(dst + ACHUNK, Bp + (size_t)it * BCHUNK, BCHUNK, bar);
    };
    if (tid == 0) { issue(0); issue(1); }

    const int nIter = K / BK;
    for (int it = 0; it < nIter; it++) {
        int s = it % NSTAGE;
        mbar_wait(sb + s * 8, (uint32_t)((it / NSTAGE) & 1));
        __syncthreads();                       // all prior-iter frag reads done -> safe reuse
        if (tid == 0 && it + 2 < nIter) issue(it + 2);
        uint32_t bA = sb + 1024 + s * STG, bB = bA + ACHUNK;
#pragma unroll
        for (int ss = 0; ss < 2; ss++) {
            int c4 = ss * 2 + (lane >> 4);
            uint32_t a[MI][4], b[8][2];
#pragma unroll
            for (int nj = 0; nj < 4; nj++) {
                int row = warpN + nj * 16 + rlo;
                uint32_t r0, r1, r2, r3;
                ldsm4(r0, r1, r2, r3, bB + row * 64 + ((c4 ^ ((row >> 1) & 3)) << 4));
                b[2 * nj][0] = r0; b[2 * nj][1] = r2;
                b[2 * nj + 1][0] = r1; b[2 * nj + 1][1] = r3;
            }
#pragma unroll
            for (int mi = 0; mi < MI; mi++) {
                int row = warpM + mi * 16 + rlo;
                ldsm4(a[mi][0], a[mi][1], a[mi][2], a[mi][3],
                      bA + row * 64 + ((c4 ^ ((row >> 1) & 3)) << 4));
            }
#pragma unroll
            for (int mi = 0; mi < MI; mi++)
#pragma unroll
                for (int ni = 0; ni < 8; ni++) mma16816(acc[mi][ni], a[mi], b[ni]);
        }
    }
    __syncthreads();   // all frag reads done before epilogue overwrites smem

    // ---------------- epilogue: lora add (+ pdn/count/flag for EPI) ----------------
    float* sL   = (float*)smem;                               // [BMT][17]
    float* sB16 = (float*)(smem + BMT * 17 * 4);              // [16][260]
    float* sWdl = (float*)(smem + BMT * 17 * 4 + 16640);      // [256][17] (EPI only)
    for (int i = tid; i < BMT * 16; i += NT) {
        int rw = i >> 4, rr = i & 15;
        sL[rw * 17 + rr] = gL[(size_t)(m0 + rw) * 16 + rr];
    }
    for (int i = tid; i < 16 * BN; i += NT) {
        int rr = i >> 8, cc = i & 255;
        sB16[rr * 260 + cc] = gBm[(size_t)rr * N + n0 + cc];
    }
    if (EPI) {
        for (int i = tid; i < BN * 16; i += NT) {
            int cc = i >> 4, rr = i & 15;
            sWdl[cc * 17 + rr] = gWdl[(size_t)(n0 + cc) * 16 + rr];
        }
    }
    __syncthreads();
    const int r = lane >> 2, cb = (lane & 3) * 2;
#pragma unroll
    for (int rr = 0; rr < 16; rr++) {
        float Lv[2 * MI];
#pragma unroll
        for (int mi = 0; mi < MI; mi++) {
            Lv[2 * mi]     = sL[(warpM + mi * 16 + r) * 17 + rr];
            Lv[2 * mi + 1] = sL[(warpM + mi * 16 + r + 8) * 17 + rr];
        }
#pragma unroll
        for (int ni = 0; ni < 8; ni++) {
            float b0v = sB16[rr * 260 + warpN + ni * 8 + cb];
            float b1v = sB16[rr * 260 + warpN + ni * 8 + cb + 1];
#pragma unroll
            for (int mi = 0; mi < MI; mi++) {
                acc[mi][ni][0] += Lv[2 * mi] * b0v;     acc[mi][ni][1] += Lv[2 * mi] * b1v;
                acc[mi][ni][2] += Lv[2 * mi + 1] * b0v; acc[mi][ni][3] += Lv[2 * mi + 1] * b1v;
            }
        }
    }

    if (EPI) {
        int bidx = m0 >> 11;
#pragma unroll
        for (int ni = 0; ni < 8; ni++) {
            int c0 = 0, c1 = 0;
#pragma unroll
            for (int mi = 0; mi < MI; mi++) {
                c0 += (acc[mi][ni][0] <= -FIX_TAU) + (acc[mi][ni][2] <= -FIX_TAU);
                c1 += (acc[mi][ni][1] <= -FIX_TAU) + (acc[mi][ni][3] <= -FIX_TAU);
            }
            int packed = c0 | (c1 << 16);
            packed += __shfl_xor_sync(0xffffffffu, packed, 4);
            packed += __shfl_xor_sync(0xffffffffu, packed, 8);
            packed += __shfl_xor_sync(0xffffffffu, packed, 16);
            if (r == 0) {
                int col = n0 + warpN + ni * 8 + cb;
                atomicAdd(&g_counts[bidx * ITR + col], packed & 0xffff);
                atomicAdd(&g_counts[bidx * ITR + col + 1], packed >> 16);
            }
        }
#pragma unroll
        for (int rr = 0; rr < 16; rr++) {
            float s[2 * MI];
#pragma unroll
            for (int j = 0; j < 2 * MI; j++) s[j] = 0.f;
#pragma unroll
            for (int ni = 0; ni < 8; ni++) {
                float w0 = sWdl[(warpN + ni * 8 + cb) * 17 + rr];
                float w1 = sWdl[(warpN + ni * 8 + cb + 1) * 17 + rr];
#pragma unroll
                for (int mi = 0; mi < MI; mi++) {
                    s[2 * mi]     += fmaxf(acc[mi][ni][0], 0.f) * w0 + fmaxf(acc[mi][ni][1], 0.f) * w1;
                    s[2 * mi + 1] += fmaxf(acc[mi][ni][2], 0.f) * w0 + fmaxf(acc[mi][ni][3], 0.f) * w1;
                }
            }
#pragma unroll
            for (int j = 0; j < 2 * MI; j++) {
                s[j] += __shfl_xor_sync(0xffffffffu, s[j], 1);
                s[j] += __shfl_xor_sync(0xffffffffu, s[j], 2);
            }
            if ((lane & 3) == 0) {
#pragma unroll
                for (int mi = 0; mi < MI; mi++) {
                    atomicAdd(&g_pdn[(m0 + warpM + mi * 16 + r) * 16 + rr], s[2 * mi]);
                    atomicAdd(&g_pdn[(m0 + warpM + mi * 16 + r + 8) * 16 + rr], s[2 * mi + 1]);
                }
            }
        }
    }

    // ---------------- writeback ----------------
#pragma unroll
    for (int mi = 0; mi < MI; mi++) {
        int row0 = m0 + warpM + mi * 16 + r;
#pragma unroll
        for (int ni = 0; ni < 8; ni++) {
            int col = n0 + warpN + ni * 8 + cb;
            if (EPI) {
                __half2 h0 = __floats2half2_rn(fmaxf(acc[mi][ni][0], 0.f), fmaxf(acc[mi][ni][1], 0.f));
                __half2 h1 = __floats2half2_rn(fmaxf(acc[mi][ni][2], 0.f), fmaxf(acc[mi][ni][3], 0.f));
                *(__half2*)(X2p + x2_off(row0, col))     = h0;
                *(__half2*)(X2p + x2_off(row0 + 8, col)) = h1;
#pragma unroll
                for (int q = 0; q < 4; q++) {
                    bool t = fabsf(acc[mi][ni][q]) < FIX_TAU;
                    unsigned msk = __ballot_sync(0xffffffffu, t);
                    if (msk) {
                        int ldr = __ffs(msk) - 1;
                        int base = 0;
                        if (lane == ldr) base = atomicAdd(&g_nflag, __popc(msk));
                        base = __shfl_sync(0xffffffffu, base, ldr);
                        if (t) {
                            int off = base + __popc(msk & ((1u << lane) - 1));
                            if (off < FLAG_CAP) {
                                g_flagm[off] = row0 + ((q >= 2) ? 8 : 0);
                                g_flagc[off] = col + (q & 1);
                            }
                        }
                    }
                }
            } else {
                *(float2*)&Y[(size_t)row0 * N + col]       = make_float2(acc[mi][ni][0], acc[mi][ni][1]);
                *(float2*)&Y[(size_t)(row0 + 8) * N + col] = make_float2(acc[mi][ni][2], acc[mi][ni][3]);
            }
        }
    }
}

// ---------------- exact fp32 recompute of flagged elements ----------------
__global__ void fixup(const float* __restrict__ x1, const float* __restrict__ wT,
                      const float* __restrict__ w_up_lb) {
    int warpId = (blockIdx.x * blockDim.x + threadIdx.x) >> 5;
    int lane = threadIdx.x & 31;
    int totalWarps = (gridDim.x * blockDim.x) >> 5;
    int n = min(g_nflag, FLAG_CAP);
    char* x2p;
    {
        // device-global address of g_x2p
        x2p = g_x2p;
    }
    for (int i = warpId; i < n; i += totalWarps) {
        int m = g_flagm[i], c = g_flagc[i];
        const float* xr = x1 + (size_t)m * HID;
        const float* wc = wT + (size_t)c * HID;
        float s = 0.f;
        for (int k = lane * 4; k < HID; k += 128) {
            float4 xv = *(const float4*)(xr + k);
            float4 wv = *(const float4*)(wc + k);
            s += xv.x * wv.x + xv.y * wv.y + xv.z * wv.z + xv.w * wv.w;
        }
#pragma unroll
        for (int o = 16; o > 0; o >>= 1) s += __shfl_xor_sync(0xffffffffu, s, o);
        if (lane == 0) {
#pragma unroll
            for (int rr = 0; rr < 16; rr++) s += g_pup[m * 16 + rr] * w_up_lb[rr * ITR + c];
            if (s <= 0.f) atomicAdd(&g_counts[(m >> 11) * ITR + c], 1);
            *(__half*)(x2p + x2_off(m, c)) = __float2half_rn(fmaxf(s, 0.f));
        }
    }
}

// ---------------- exact top-10 smallest (count, index) ----------------
__global__ void topk_kernel() {
    __shared__ int red[256];
    int b = blockIdx.x, tid = threadIdx.x;
    int prev = -1;
    for (int r = 0; r < KSAVE; r++) {
        int best = 0x7fffffff;
        for (int c = tid; c < ITR; c += 256) {
            int key = (g_counts[b * ITR + c] << 13) | c;
            if (key > prev && key < best) best = key;
        }
        red[tid] = best;
        __syncthreads();
        for (int s = 128; s > 0; s >>= 1) {
            if (tid < s) red[tid] = min(red[tid], red[tid + s]);
            __syncthreads();
        }
        prev = red[0];
        if (tid == 0) g_topk[b * KSAVE + r] = prev & 8191;
        __syncthreads();
    }
}

// ---------------- gather ----------------
__global__ void gather_save(float* __restrict__ outp) {
    int i = blockIdx.x * 256 + threadIdx.x;
    if (i >= NB * SEQ * KSAVE) return;
    int j = i % KSAVE;
    int s = (i / KSAVE) % SEQ;
    int b = i / (KSAVE * SEQ);
    int c = g_topk[b * KSAVE + j];
    int m = b * SEQ + s;
    outp[i] = __half2float(*(__half*)(g_x2p + x2_off(m, c)));
}

// ---------------- launch ----------------
extern "C" void kernel_launch(void* const* d_in, const int* in_sizes, int n_in,
                              void* d_out, int out_size) {
    const float* x1      = (const float*)d_in[0];
    const float* w_up    = (const float*)d_in[1];
    const float* w_up_la = (const float*)d_in[2];
    const float* w_up_lb = (const float*)d_in[3];
    const float* w_down  = (const float*)d_in[4];
    const float* w_dn_la = (const float*)d_in[5];
    const float* w_dn_lb = (const float*)d_in[6];
    float* out = (float*)d_out;

    float *pup, *pdn, *wupT32;
    char *x1p, *wupP, *wdnP, *x2p;
    cudaGetSymbolAddress((void**)&pup, g_pup);
    cudaGetSymbolAddress((void**)&pdn, g_pdn);
    cudaGetSymbolAddress((void**)&x1p, g_x1p);
    cudaGetSymbolAddress((void**)&wupP, g_wupP);
    cudaGetSymbolAddress((void**)&wdnP, g_wdnP);
    cudaGetSymbolAddress((void**)&x2p, g_x2p);
    cudaGetSymbolAddress((void**)&wupT32, g_wupT32);

    constexpr int DS1 = 1024 + NSTAGE * (128 * 64 + BCHUNK);   // 74752
    constexpr int DS2 = 1024 + NSTAGE * (64 * 64 + BCHUNK);    // 62464
    cudaFuncSetAttribute(gemm_f16<128, 0, 1>, cudaFuncAttributeMaxDynamicSharedMemorySize, DS1);
    cudaFuncSetAttribute(gemm_f16<64, 1, 0>, cudaFuncAttributeMaxDynamicSharedMemorySize, DS2);

    // launch order: gemm1 is the 4th launch => profiled by ncu (-s window)
    lora_proj_init<<<MTOK / 16, 256>>>(x1, w_up_la, pup, HID);                          // 1
    pack_A<<<dim3(MTOK / 128, HID / 32), 256>>>(x1, x1p, HID);                          // 2
    pack_B<1><<<dim3(ITR / 256, HID / 32), 256>>>(w_up, wupP, wupT32, HID, ITR);        // 3
    gemm_f16<128, 0, 1><<<dim3(MTOK / 128, ITR / BN), NT, DS1>>>(                       // 4 <- profiled
        x1p, wupP, pup, w_up_lb, w_dn_la, (float*)nullptr, x2p, MTOK, ITR, HID);

    pack_B<0><<<dim3(HID / 256, ITR / 32), 256>>>(w_down, wdnP, (float*)nullptr, ITR, HID); // 5
    fixup<<<512, 256>>>(x1, wupT32, w_up_lb);                                           // 6
    topk_kernel<<<NB, 256>>>();                                                         // 7
    gemm_f16<64, 1, 0><<<dim3(HID / BN, MTOK / 64), NT, DS2>>>(                         // 8
        x2p, wdnP, pdn, w_dn_lb, (float*)nullptr, out, (char*)nullptr, MTOK, HID, ITR);

    int save_elems = NB * SEQ * KSAVE;
    gather_save<<<(save_elems + 255) / 256, 256>>>(out + (out_size - save_elems));      // 9
}